// round 16
// baseline (speedup 1.0000x reference)
#include <cuda_runtime.h>
#include <cuda_fp16.h>
#include <cstdint>

#define DIM    1536
#define HEADS  12
#define HD     128
#define LTOK   3520
#define EPS    1e-6f
#define SCALE  0.08838834764831845f   // 1/sqrt(128)
#define LOG2E  1.4426950408889634f

// ---------------- scratch (no allocation allowed) ----------------
__device__ float  g_p0[LTOK * DIM];   // split-K out partial 0
__device__ float  g_p1[LTOK * DIM];   // split-K out partial 1
__device__ __half g_xt[LTOK * DIM];
__device__ __half g_wt[4][DIM * DIM];
__device__ __half g_qh[LTOK * DIM];   // raw q (fp16, from gemm)
__device__ __half g_kh[LTOK * DIM];   // raw k
__device__ __half g_qt[LTOK * DIM];   // rmsnorm+rope q, *SCALE*log2e
__device__ __half g_kt[LTOK * DIM];   // rmsnorm+rope k
__device__ __half g_vt[LTOK * DIM];   // v
__device__ __half g_ot[LTOK * DIM];   // attention output

// ---------------- helpers ----------------
__device__ __forceinline__ void mma_f16(float c[4],
    uint32_t a0, uint32_t a1, uint32_t a2, uint32_t a3,
    uint32_t b0, uint32_t b1)
{
    asm volatile(
        "mma.sync.aligned.m16n8k16.row.col.f32.f16.f16.f32 "
        "{%0,%1,%2,%3}, {%4,%5,%6,%7}, {%8,%9}, {%0,%1,%2,%3};\n"
        : "+f"(c[0]), "+f"(c[1]), "+f"(c[2]), "+f"(c[3])
        : "r"(a0), "r"(a1), "r"(a2), "r"(a3), "r"(b0), "r"(b1));
}
__device__ __forceinline__ void ldsm_x4(uint32_t& r0, uint32_t& r1,
                                        uint32_t& r2, uint32_t& r3, uint32_t addr)
{
    asm volatile("ldmatrix.sync.aligned.m8n8.x4.shared.b16 {%0,%1,%2,%3}, [%4];"
                 : "=r"(r0), "=r"(r1), "=r"(r2), "=r"(r3) : "r"(addr));
}
__device__ __forceinline__ void ldsm_x4_t(uint32_t& r0, uint32_t& r1,
                                          uint32_t& r2, uint32_t& r3, uint32_t addr)
{
    asm volatile("ldmatrix.sync.aligned.m8n8.x4.trans.shared.b16 {%0,%1,%2,%3}, [%4];"
                 : "=r"(r0), "=r"(r1), "=r"(r2), "=r"(r3) : "r"(addr));
}
__device__ __forceinline__ uint32_t smem_addr(const void* p) {
    return (uint32_t)__cvta_generic_to_shared(p);
}
__device__ __forceinline__ void cp_async16(uint32_t dst, const void* src) {
    asm volatile("cp.async.cg.shared.global [%0], [%1], 16;" :: "r"(dst), "l"(src));
}
#define CP_COMMIT() asm volatile("cp.async.commit_group;" ::: "memory")
#define CP_WAIT1()  asm volatile("cp.async.wait_group 1;" ::: "memory")

__device__ __forceinline__ uint32_t h2exp2(uint32_t x) {
    uint32_t r;
    asm("ex2.approx.f16x2 %0, %1;" : "=r"(r) : "r"(x));
    return r;
}

// ================= converts =================
__global__ void __launch_bounds__(256) convert_f16(const float4* __restrict__ src,
                                                   uint2* __restrict__ dst, int n4)
{
    int i = blockIdx.x * blockDim.x + threadIdx.x;
    if (i < n4) {
        float4 v = src[i];
        __half2 lo = __floats2half2_rn(v.x, v.y);
        __half2 hi = __floats2half2_rn(v.z, v.w);
        dst[i] = make_uint2(*(uint32_t*)&lo, *(uint32_t*)&hi);
    }
}

__global__ void __launch_bounds__(256) convert_w4(
    const float4* __restrict__ Wq, const float4* __restrict__ Wk,
    const float4* __restrict__ Wv, const float4* __restrict__ Wo,
    uint2* __restrict__ dst, int nw4)
{
    int i = blockIdx.x * blockDim.x + threadIdx.x;
    if (i >= 4 * nw4) return;
    int w = i / nw4, j = i - w * nw4;
    const float4* src = (w == 0) ? Wq : (w == 1) ? Wk : (w == 2) ? Wv : Wo;
    float4 v = src[j];
    __half2 lo = __floats2half2_rn(v.x, v.y);
    __half2 hi = __floats2half2_rn(v.z, v.w);
    dst[i] = make_uint2(*(uint32_t*)&lo, *(uint32_t*)&hi);
}

// ============ reduce: out = p0 + p1 + bias =============================
__global__ void __launch_bounds__(256) reduce_bias(
    const float4* __restrict__ p0, const float4* __restrict__ p1,
    const float4* __restrict__ bias, float4* __restrict__ out, int n4)
{
    int i = blockIdx.x * blockDim.x + threadIdx.x;
    if (i < n4) {
        float4 a = p0[i], b = p1[i], bb = bias[i % (DIM / 4)];
        out[i] = make_float4(a.x + b.x + bb.x, a.y + b.y + bb.y,
                             a.z + b.z + bb.z, a.w + b.w + bb.w);
    }
}

// ================= fp16 GEMM core =================
#define GM_BM 128
#define GM_BN 128
#define GM_BK 64
#define GSTR_H 72
#define GM_TILE_H (GM_BM * GSTR_H)
#define GM_STAGE_H (2 * GM_TILE_H)
#define GM_SMEM_BYTES (3 * GM_STAGE_H * 2)   // 110592

__device__ __forceinline__ void gemm_tile_f16(
    const __half* __restrict__ A, const __half* __restrict__ B,
    const float* __restrict__ bias, float* __restrict__ Cf, __half* __restrict__ Ch,
    int M, int N, int K, int kbeg, int klen, int m0, int n0, __half* sm)
{
    const int tid = threadIdx.x;
    const int lane = tid & 31;
    const int wid = tid >> 5;
    const int wm = wid >> 2;
    const int wn = wid & 3;

    const int tr = lane & 7;
    const int mq = lane >> 3;
    const int a_row = tr + 8 * (mq & 1);
    const int a_kb  = 16 * (mq >> 1);
    const int b_row = tr + 8 * (mq >> 1);
    const int b_kb  = 16 * (mq & 1);

    int r2[4], kc2[4], arow[4], brow[4];
#pragma unroll
    for (int i = 0; i < 4; ++i) {
        int s = tid + i * 256;
        r2[i] = s >> 3;
        kc2[i] = (s & 7) * 8;
        arow[i] = min(m0 + r2[i], M - 1);
        brow[i] = n0 + r2[i];
    }

    const uint32_t smu = smem_addr(sm);

    auto fill = [&](int st, int k0) {
        const uint32_t base = smu + 2u * (st * GM_STAGE_H);
#pragma unroll
        for (int i = 0; i < 4; ++i)
            cp_async16(base + 2u * (r2[i] * GSTR_H + kc2[i]),
                       A + (size_t)arow[i] * K + k0 + kc2[i]);
#pragma unroll
        for (int i = 0; i < 4; ++i)
            cp_async16(base + 2u * (GM_TILE_H + r2[i] * GSTR_H + kc2[i]),
                       B + (size_t)brow[i] * K + k0 + kc2[i]);
        CP_COMMIT();
    };

    fill(0, kbeg);
    fill(1, kbeg + GM_BK);

    float acc[16][4];
#pragma unroll
    for (int t = 0; t < 16; ++t)
        acc[t][0] = acc[t][1] = acc[t][2] = acc[t][3] = 0.f;

    const int NIT = klen / GM_BK;
    int st = 0;
    for (int it = 0; it < NIT; ++it) {
        CP_WAIT1();
        __syncthreads();
        if (it + 2 < NIT) fill((st + 2) % 3, kbeg + (it + 2) * GM_BK);
        else CP_COMMIT();

        const uint32_t Ab = smu + 2u * (st * GM_STAGE_H);
        const uint32_t Bb = Ab + 2u * GM_TILE_H;
#pragma unroll
        for (int ks = 0; ks < 4; ++ks) {
            const int kbb = ks * 32;
            uint32_t af[4][4], bf[4][2];
#pragma unroll
            for (int mt = 0; mt < 4; ++mt) {
                uint32_t addr = Ab + (wm * 64 + mt * 16 + a_row) * (GSTR_H * 2) + kbb + a_kb;
                ldsm_x4(af[mt][0], af[mt][1], af[mt][2], af[mt][3], addr);
            }
#pragma unroll
            for (int p = 0; p < 2; ++p) {
                uint32_t addr = Bb + (wn * 32 + p * 16 + b_row) * (GSTR_H * 2) + kbb + b_kb;
                ldsm_x4(bf[2*p][0], bf[2*p][1], bf[2*p+1][0], bf[2*p+1][1], addr);
            }
#pragma unroll
            for (int mt = 0; mt < 4; ++mt)
#pragma unroll
                for (int nt = 0; nt < 4; ++nt)
                    mma_f16(acc[mt * 4 + nt],
                            af[mt][0], af[mt][1], af[mt][2], af[mt][3],
                            bf[nt][0], bf[nt][1]);
        }
        st = (st + 1) % 3;
    }

    // epilogue
#pragma unroll
    for (int nt = 0; nt < 4; ++nt) {
        int c = n0 + wn * 32 + nt * 8 + (lane & 3) * 2;
        float b0 = 0.f, b1 = 0.f;
        if (bias) { b0 = bias[c]; b1 = bias[c + 1]; }
#pragma unroll
        for (int mt = 0; mt < 4; ++mt) {
            int r = m0 + wm * 64 + mt * 16 + (lane >> 2);
            float* a4 = acc[mt * 4 + nt];
            if (Ch) {
                if (r < M)
                    *(__half2*)(Ch + (size_t)r * N + c) = __floats2half2_rn(a4[0] + b0, a4[1] + b1);
                if (r + 8 < M)
                    *(__half2*)(Ch + (size_t)(r + 8) * N + c) = __floats2half2_rn(a4[2] + b0, a4[3] + b1);
            } else {
                if (r < M)
                    *(float2*)(Cf + (size_t)r * N + c) = make_float2(a4[0] + b0, a4[1] + b1);
                if (r + 8 < M)
                    *(float2*)(Cf + (size_t)(r + 8) * N + c) = make_float2(a4[2] + b0, a4[3] + b1);
            }
        }
    }
}

__global__ void __launch_bounds__(256, 2) qkv_gemm_f16(
    const float* __restrict__ bq, const float* __restrict__ bk,
    const float* __restrict__ bv)
{
    extern __shared__ __align__(16) __half smh[];
    const float* b; __half* outH;
    if (blockIdx.z == 0)      { b = bq; outH = g_qh; }
    else if (blockIdx.z == 1) { b = bk; outH = g_kh; }
    else                      { b = bv; outH = g_vt; }
    gemm_tile_f16(g_xt, g_wt[blockIdx.z], b, nullptr, outH, LTOK, DIM, DIM,
                  0, DIM, blockIdx.y * GM_BM, blockIdx.x * GM_BN, smh);
}

__global__ void __launch_bounds__(256, 2) out_gemm_f16()
{
    extern __shared__ __align__(16) __half smh[];
    float* part = blockIdx.z ? g_p1 : g_p0;
    gemm_tile_f16(g_ot, g_wt[3], nullptr, part, nullptr, LTOK, DIM, DIM,
                  blockIdx.z * (DIM / 2), DIM / 2,
                  blockIdx.y * GM_BM, blockIdx.x * GM_BN, smh);
}

// ============ fused RMSNorm + RoPE (fp16 in/out, q pre-scaled) ===========
__global__ void __launch_bounds__(256) rmsnorm_rope(
    const float* __restrict__ gq, const float* __restrict__ gk,
    const float* __restrict__ freqs, const int* __restrict__ gsz)
{
    const int t = blockIdx.x;
    const int which = blockIdx.y;
    const __half* row = (which ? g_kh : g_qh) + (size_t)t * DIM;
    __half* rowo = (which ? g_kt : g_qt) + (size_t)t * DIM;
    const float oscale = which ? 1.0f : (SCALE * LOG2E);
    const float* g = which ? gk : gq;
    const int tid = threadIdx.x;

    float ss = 0.f;
    for (int i = tid; i < DIM / 2; i += 256) {
        float2 v = __half22float2(((const __half2*)row)[i]);
        ss += v.x * v.x + v.y * v.y;
    }
    __shared__ float red[8];
#pragma unroll
    for (int o = 16; o; o >>= 1) ss += __shfl_xor_sync(0xffffffffu, ss, o);
    if ((tid & 31) == 0) red[tid >> 5] = ss;
    __syncthreads();
    if (tid < 8) {
        float v = red[tid];
#pragma unroll
        for (int o = 4; o; o >>= 1) v += __shfl_xor_sync(0xffu, v, o);
        if (tid == 0) red[0] = v;
    }
    __syncthreads();
    const float rms = rsqrtf(red[0] * (1.0f / DIM) + EPS);

    const int Hs = gsz[1], Ws = gsz[2];
    const int fi = t / (Hs * Ws);
    const int hi = (t / Ws) % Hs;
    const int wi = t % Ws;

    for (int p = tid; p < HEADS * 64; p += 256) {
        const int h = p >> 6;
        const int j = p & 63;
        const int pos = (j < 22) ? fi : ((j < 43) ? hi : wi);
        const float ang = freqs[pos * 64 + j];
        float c, s;
        sincosf(ang, &s, &c);
        const int d0 = h * HD + 2 * j;
        float2 xv = __half22float2(*(const __half2*)(row + d0));
        const float x0 = xv.x * rms * g[d0];
        const float x1 = xv.y * rms * g[d0 + 1];
        __half2 o = __floats2half2_rn((x0 * c - x1 * s) * oscale,
                                      (x0 * s + x1 * c) * oscale);
        *(__half2*)(rowo + d0) = o;
    }
}

// ====== flash attention: BQ=128, 512 threads (4x4 warps), fp16 mma ======
#define FQ 128
#define FK 64
#define TST_H 136
#define SST_H 72
// Q 128 rows + K0/K1/V 64 rows + P 128 rows + m/l/pm/ps
#define FLASH_SMEM_BYTES (FQ*TST_H*2 + 3*FK*TST_H*2 + FQ*SST_H*2 + (2*FQ + 8*FQ)*4)

__global__ void __launch_bounds__(512, 1) flash_f16()
{
    extern __shared__ __align__(16) char smc[];
    __half* Qs = (__half*)smc;
    __half* K0 = Qs + FQ * TST_H;
    __half* K1 = K0 + FK * TST_H;
    __half* Vs = K1 + FK * TST_H;
    __half* Ss = Vs + FK * TST_H;
    float* m_s = (float*)(Ss + FQ * SST_H);
    float* l_s = m_s + FQ;
    float* pm  = l_s + FQ;          // [128][4]
    float* ps  = pm + FQ * 4;       // [128][4]

    const int tid = threadIdx.x;
    const int lane = tid & 31;
    const int wid = tid >> 5;       // 0..15
    const int wm = wid >> 2;        // 0..3 (q quarter)
    const int wn = wid & 3;         // 0..3
    const int h  = blockIdx.y;
    const int q0 = blockIdx.x * FQ;

    const int tr = lane & 7;
    const int mq = lane >> 3;
    const int a_row = tr + 8 * (mq & 1);
    const int a_kb  = 16 * (mq >> 1);
    const int b_row = tr + 8 * (mq >> 1);
    const int b_kb  = 16 * (mq & 1);
    const int v_krow = tr + 8 * (mq & 1);
    const int v_noff = 8 * (mq >> 1);

    const uint32_t Qa = smem_addr(Qs);
    const uint32_t K0a = smem_addr(K0);
    const uint32_t K1a = smem_addr(K1);
    const uint32_t Va = smem_addr(Vs);
    const uint32_t Sa = smem_addr(Ss);

    // Q staging: 128 rows x 16 uint4 = 2048 chunks / 512 thr = 4 each
    // KV staging: 64 rows x 16 = 1024 / 512 = 2 each
    int qrow[4], qcol[4];
#pragma unroll
    for (int j = 0; j < 4; ++j) {
        int i = tid + j * 512;
        qrow[j] = i >> 4;
        qcol[j] = (i & 15) * 8;
    }
    int krow[2], kcol[2];
#pragma unroll
    for (int j = 0; j < 2; ++j) {
        int i = tid + j * 512;
        krow[j] = i >> 4;
        kcol[j] = (i & 15) * 8;
    }

    // Q tile (clamped rows for last tile) + K(0)
#pragma unroll
    for (int j = 0; j < 4; ++j) {
        int qr = min(q0 + qrow[j], LTOK - 1);
        uint4 v = *(const uint4*)(g_qt + (size_t)qr * DIM + h * HD + qcol[j]);
        *(uint4*)&Qs[qrow[j] * TST_H + qcol[j]] = v;
    }
#pragma unroll
    for (int j = 0; j < 2; ++j) {
        uint4 kv = *(const uint4*)(g_kt + (size_t)krow[j] * DIM + h * HD + kcol[j]);
        *(uint4*)&K0[krow[j] * TST_H + kcol[j]] = kv;
    }
    if (tid < FQ) { m_s[tid] = -3.0e38f; l_s[tid] = 0.f; }

    float O[8][4];
#pragma unroll
    for (int t = 0; t < 8; ++t) O[t][0] = O[t][1] = O[t][2] = O[t][3] = 0.f;

    __syncthreads();

    int it = 0;
    for (int t0 = 0; t0 < LTOK; t0 += FK, ++it) {
        const uint32_t Kcur = (it & 1) ? K1a : K0a;
        __half* Knext = (it & 1) ? K0 : K1;

        uint4 vreg[2], kreg[2];
#pragma unroll
        for (int j = 0; j < 2; ++j)
            vreg[j] = *(const uint4*)(g_vt + (size_t)(t0 + krow[j]) * DIM + h * HD + kcol[j]);
        const bool has_next = (t0 + FK < LTOK);
        if (has_next) {
#pragma unroll
            for (int j = 0; j < 2; ++j)
                kreg[j] = *(const uint4*)(g_kt + (size_t)(t0 + FK + krow[j]) * DIM + h * HD + kcol[j]);
        }

        // S = Q K^T (log2-domain, fp32 accum): warp tile 32(q) x 16(kv)
        float Sacc[2][2][4] = {};
#pragma unroll
        for (int ks = 0; ks < 8; ++ks) {
            const int kbb = ks * 32;
            uint32_t af[2][4], bf[2][2];
#pragma unroll
            for (int mt = 0; mt < 2; ++mt) {
                uint32_t addr = Qa + (wm * 32 + mt * 16 + a_row) * (TST_H * 2) + kbb + a_kb;
                ldsm_x4(af[mt][0], af[mt][1], af[mt][2], af[mt][3], addr);
            }
            {
                uint32_t addr = Kcur + (wn * 16 + b_row) * (TST_H * 2) + kbb + b_kb;
                ldsm_x4(bf[0][0], bf[0][1], bf[1][0], bf[1][1], addr);
            }
#pragma unroll
            for (int mt = 0; mt < 2; ++mt)
#pragma unroll
                for (int nt = 0; nt < 2; ++nt)
                    mma_f16(Sacc[mt][nt],
                            af[mt][0], af[mt][1], af[mt][2], af[mt][3],
                            bf[nt][0], bf[nt][1]);
        }

        // warp-partial row max
        float pmax[2][2];
#pragma unroll
        for (int mt = 0; mt < 2; ++mt) {
            pmax[mt][0] = fmaxf(fmaxf(Sacc[mt][0][0], Sacc[mt][0][1]),
                                fmaxf(Sacc[mt][1][0], Sacc[mt][1][1]));
            pmax[mt][1] = fmaxf(fmaxf(Sacc[mt][0][2], Sacc[mt][0][3]),
                                fmaxf(Sacc[mt][1][2], Sacc[mt][1][3]));
#pragma unroll
            for (int rs = 0; rs < 2; ++rs) {
                pmax[mt][rs] = fmaxf(pmax[mt][rs], __shfl_xor_sync(0xffffffffu, pmax[mt][rs], 1));
                pmax[mt][rs] = fmaxf(pmax[mt][rs], __shfl_xor_sync(0xffffffffu, pmax[mt][rs], 2));
            }
        }
        if ((lane & 3) == 0) {
#pragma unroll
            for (int mt = 0; mt < 2; ++mt)
#pragma unroll
                for (int rs = 0; rs < 2; ++rs) {
                    int row = wm * 32 + mt * 16 + (lane >> 2) + rs * 8;
                    pm[row * 4 + wn] = pmax[mt][rs];
                }
        }
        __syncthreads();   // A: pm visible; V + K-next buffers free

        // commit V(t), K(t+1)
#pragma unroll
        for (int j = 0; j < 2; ++j)
            *(uint4*)&Vs[krow[j] * TST_H + kcol[j]] = vreg[j];
        if (has_next) {
#pragma unroll
            for (int j = 0; j < 2; ++j)
                *(uint4*)&Knext[krow[j] * TST_H + kcol[j]] = kreg[j];
        }

        // softmax: mnew, f, P via ex2.f16x2
        float mnew[2][2], fsc[2][2], psum[2][2];
#pragma unroll
        for (int mt = 0; mt < 2; ++mt)
#pragma unroll
            for (int rs = 0; rs < 2; ++rs) {
                int row = wm * 32 + mt * 16 + (lane >> 2) + rs * 8;
                float4 pv = *(float4*)&pm[row * 4];
                float mold = m_s[row];
                float mx = fmaxf(fmaxf(pv.x, pv.y), fmaxf(pv.z, pv.w));
                float mn = fmaxf(mold, mx);
                mnew[mt][rs] = mn;
                fsc[mt][rs] = exp2f(mold - mn);
                psum[mt][rs] = 0.f;
            }
#pragma unroll
        for (int mt = 0; mt < 2; ++mt) {
            int r = wm * 32 + mt * 16 + (lane >> 2);
            int c = wn * 16 + (lane & 3) * 2;
#pragma unroll
            for (int nt = 0; nt < 2; ++nt) {
                __half2 s0 = __floats2half2_rn(Sacc[mt][nt][0] - mnew[mt][0],
                                               Sacc[mt][nt][1] - mnew[mt][0]);
                __half2 s1 = __floats2half2_rn(Sacc[mt][nt][2] - mnew[mt][1],
                                               Sacc[mt][nt][3] - mnew[mt][1]);
                uint32_t p0 = h2exp2(*(uint32_t*)&s0);
                uint32_t p1 = h2exp2(*(uint32_t*)&s1);
                *(uint32_t*)&Ss[r * SST_H + c + nt * 8] = p0;
                *(uint32_t*)&Ss[(r + 8) * SST_H + c + nt * 8] = p1;
                float2 f0 = __half22float2(*(__half2*)&p0);
                float2 f1 = __half22float2(*(__half2*)&p1);
                psum[mt][0] += f0.x + f0.y;
                psum[mt][1] += f1.x + f1.y;
            }
        }
#pragma unroll
        for (int mt = 0; mt < 2; ++mt)
#pragma unroll
            for (int rs = 0; rs < 2; ++rs) {
                psum[mt][rs] += __shfl_xor_sync(0xffffffffu, psum[mt][rs], 1);
                psum[mt][rs] += __shfl_xor_sync(0xffffffffu, psum[mt][rs], 2);
            }
        if ((lane & 3) == 0) {
#pragma unroll
            for (int mt = 0; mt < 2; ++mt)
#pragma unroll
                for (int rs = 0; rs < 2; ++rs) {
                    int row = wm * 32 + mt * 16 + (lane >> 2) + rs * 8;
                    ps[row * 4 + wn] = psum[mt][rs];
                }
        }

        // O rescale
#pragma unroll
        for (int mt = 0; mt < 2; ++mt) {
            float f0 = fsc[mt][0], f1 = fsc[mt][1];
#pragma unroll
            for (int nt = 0; nt < 4; ++nt) {
                O[mt * 4 + nt][0] *= f0; O[mt * 4 + nt][1] *= f0;
                O[mt * 4 + nt][2] *= f1; O[mt * 4 + nt][3] *= f1;
            }
        }
        __syncthreads();   // B: P, ps, V, K-next visible

        if (wn == 0 && (lane & 3) == 0) {
#pragma unroll
            for (int mt = 0; mt < 2; ++mt)
#pragma unroll
                for (int rs = 0; rs < 2; ++rs) {
                    int row = wm * 32 + mt * 16 + (lane >> 2) + rs * 8;
                    float4 s4 = *(float4*)&ps[row * 4];
                    l_s[row] = l_s[row] * fsc[mt][rs] + (s4.x + s4.y + s4.z + s4.w);
                    m_s[row] = mnew[mt][rs];
                }
        }

        // O += P @ V : warp tile 32(q) x 32(hd)
#pragma unroll
        for (int ks = 0; ks < 4; ++ks) {
            const int kb = ks * 16;
            uint32_t af[2][4], bf[4][2];
#pragma unroll
            for (int mt = 0; mt < 2; ++mt) {
                uint32_t addr = Sa + (wm * 32 + mt * 16 + a_row) * (SST_H * 2) + ks * 32 + a_kb;
                ldsm_x4(af[mt][0], af[mt][1], af[mt][2], af[mt][3], addr);
            }
#pragma unroll
            for (int p = 0; p < 2; ++p) {
                int c0 = wn * 32 + p * 16;
                uint32_t addr = Va + (kb + v_krow) * (TST_H * 2) + (c0 + v_noff) * 2;
                ldsm_x4_t(bf[2*p][0], bf[2*p][1], bf[2*p+1][0], bf[2*p+1][1], addr);
            }
#pragma unroll
            for (int mt = 0; mt < 2; ++mt)
#pragma unroll
                for (int nt = 0; nt < 4; ++nt)
                    mma_f16(O[mt * 4 + nt],
                            af[mt][0], af[mt][1], af[mt][2], af[mt][3],
                            bf[nt][0], bf[nt][1]);
        }
    }

    __syncthreads();

    // finalize -> fp16 g_ot (guarded rows for last tile)
#pragma unroll
    for (int mt = 0; mt < 2; ++mt) {
        int r = wm * 32 + mt * 16 + (lane >> 2);
        float inv0 = 1.f / l_s[r], inv1 = 1.f / l_s[r + 8];
#pragma unroll
        for (int nt = 0; nt < 4; ++nt) {
            int c = wn * 32 + nt * 8 + (lane & 3) * 2;
            float* a4 = O[mt * 4 + nt];
            if (q0 + r < LTOK)
                *(__half2*)(g_ot + (size_t)(q0 + r) * DIM + h * HD + c) =
                    __floats2half2_rn(a4[0] * inv0, a4[1] * inv0);
            if (q0 + r + 8 < LTOK)
                *(__half2*)(g_ot + (size_t)(q0 + r + 8) * DIM + h * HD + c) =
                    __floats2half2_rn(a4[2] * inv1, a4[3] * inv1);
        }
    }
}

// ================= launch =================
extern "C" void kernel_launch(void* const* d_in, const int* in_sizes, int n_in,
                              void* d_out, int out_size)
{
    const float* x          = (const float*)d_in[0];
    const int*   grid_sizes = (const int*)d_in[2];
    const float* freqs      = (const float*)d_in[3];
    const float* Wq = (const float*)d_in[4];
    const float* bq = (const float*)d_in[5];
    const float* Wk = (const float*)d_in[6];
    const float* bk = (const float*)d_in[7];
    const float* Wv = (const float*)d_in[8];
    const float* bv = (const float*)d_in[9];
    const float* Wo = (const float*)d_in[10];
    const float* bo = (const float*)d_in[11];
    const float* gq = (const float*)d_in[12];
    const float* gk = (const float*)d_in[13];
    float* out = (float*)d_out;

    __half *xt, *wt;
    float *p0, *p1;
    cudaGetSymbolAddress((void**)&xt, g_xt);
    cudaGetSymbolAddress((void**)&wt, g_wt);
    cudaGetSymbolAddress((void**)&p0, g_p0);
    cudaGetSymbolAddress((void**)&p1, g_p1);

    cudaFuncSetAttribute(flash_f16, cudaFuncAttributeMaxDynamicSharedMemorySize, FLASH_SMEM_BYTES);
    cudaFuncSetAttribute(qkv_gemm_f16, cudaFuncAttributeMaxDynamicSharedMemorySize, GM_SMEM_BYTES);
    cudaFuncSetAttribute(out_gemm_f16, cudaFuncAttributeMaxDynamicSharedMemorySize, GM_SMEM_BYTES);

    const int NX4 = LTOK * DIM / 4;
    const int NW4 = DIM * DIM / 4;

    convert_f16<<<(NX4 + 255) / 256, 256>>>((const float4*)x, (uint2*)xt, NX4);
    convert_w4<<<(4 * NW4 + 255) / 256, 256>>>((const float4*)Wq, (const float4*)Wk,
                                               (const float4*)Wv, (const float4*)Wo,
                                               (uint2*)wt, NW4);

    dim3 gqkv(DIM / GM_BN, (LTOK + GM_BM - 1) / GM_BM, 3);
    dim3 gout(DIM / GM_BN, (LTOK + GM_BM - 1) / GM_BM, 2);

    qkv_gemm_f16<<<gqkv, 256, GM_SMEM_BYTES>>>(bq, bk, bv);
    rmsnorm_rope<<<dim3(LTOK, 2), 256>>>(gq, gk, freqs, grid_sizes);
    flash_f16<<<dim3((LTOK + FQ - 1) / FQ, HEADS), 512, FLASH_SMEM_BYTES>>>();
    out_gemm_f16<<<gout, 256, GM_SMEM_BYTES>>>();
    reduce_bias<<<(NX4 + 255) / 256, 256>>>((const float4*)p0, (const float4*)p1,
                                            (const float4*)bo, (float4*)out, NX4);
}

// round 17
// speedup vs baseline: 1.0841x; 1.0841x over previous
#include <cuda_runtime.h>
#include <cuda_fp16.h>
#include <cstdint>

#define DIM    1536
#define HEADS  12
#define HD     128
#define LTOK   3520
#define EPS    1e-6f
#define SCALE  0.08838834764831845f   // 1/sqrt(128)
#define LOG2E  1.4426950408889634f

// ---------------- scratch (no allocation allowed) ----------------
__device__ float  g_p0[LTOK * DIM];   // split-K out partial 0
__device__ float  g_p1[LTOK * DIM];   // split-K out partial 1
__device__ __half g_xt[LTOK * DIM];
__device__ __half g_wt[4][DIM * DIM];
__device__ __half g_qh[LTOK * DIM];   // raw q (fp16, from gemm)
__device__ __half g_kh[LTOK * DIM];   // raw k
__device__ __half g_qt[LTOK * DIM];   // rmsnorm+rope q, *SCALE*log2e
__device__ __half g_kt[LTOK * DIM];   // rmsnorm+rope k
__device__ __half g_vt[LTOK * DIM];   // v
__device__ __half g_ot[LTOK * DIM];   // attention output

// ---------------- helpers ----------------
__device__ __forceinline__ void mma_f16(float c[4],
    uint32_t a0, uint32_t a1, uint32_t a2, uint32_t a3,
    uint32_t b0, uint32_t b1)
{
    asm volatile(
        "mma.sync.aligned.m16n8k16.row.col.f32.f16.f16.f32 "
        "{%0,%1,%2,%3}, {%4,%5,%6,%7}, {%8,%9}, {%0,%1,%2,%3};\n"
        : "+f"(c[0]), "+f"(c[1]), "+f"(c[2]), "+f"(c[3])
        : "r"(a0), "r"(a1), "r"(a2), "r"(a3), "r"(b0), "r"(b1));
}
__device__ __forceinline__ void ldsm_x4(uint32_t& r0, uint32_t& r1,
                                        uint32_t& r2, uint32_t& r3, uint32_t addr)
{
    asm volatile("ldmatrix.sync.aligned.m8n8.x4.shared.b16 {%0,%1,%2,%3}, [%4];"
                 : "=r"(r0), "=r"(r1), "=r"(r2), "=r"(r3) : "r"(addr));
}
__device__ __forceinline__ void ldsm_x4_t(uint32_t& r0, uint32_t& r1,
                                          uint32_t& r2, uint32_t& r3, uint32_t addr)
{
    asm volatile("ldmatrix.sync.aligned.m8n8.x4.trans.shared.b16 {%0,%1,%2,%3}, [%4];"
                 : "=r"(r0), "=r"(r1), "=r"(r2), "=r"(r3) : "r"(addr));
}
__device__ __forceinline__ uint32_t smem_addr(const void* p) {
    return (uint32_t)__cvta_generic_to_shared(p);
}
__device__ __forceinline__ void cp_async16(uint32_t dst, const void* src) {
    asm volatile("cp.async.cg.shared.global [%0], [%1], 16;" :: "r"(dst), "l"(src));
}
#define CP_COMMIT() asm volatile("cp.async.commit_group;" ::: "memory")
#define CP_WAIT1()  asm volatile("cp.async.wait_group 1;" ::: "memory")

__device__ __forceinline__ uint32_t h2exp2(uint32_t x) {
    uint32_t r;
    asm("ex2.approx.f16x2 %0, %1;" : "=r"(r) : "r"(x));
    return r;
}

// ================= converts =================
__global__ void __launch_bounds__(256) convert_f16(const float4* __restrict__ src,
                                                   uint2* __restrict__ dst, int n4)
{
    int i = blockIdx.x * blockDim.x + threadIdx.x;
    if (i < n4) {
        float4 v = src[i];
        __half2 lo = __floats2half2_rn(v.x, v.y);
        __half2 hi = __floats2half2_rn(v.z, v.w);
        dst[i] = make_uint2(*(uint32_t*)&lo, *(uint32_t*)&hi);
    }
}

__global__ void __launch_bounds__(256) convert_w4(
    const float4* __restrict__ Wq, const float4* __restrict__ Wk,
    const float4* __restrict__ Wv, const float4* __restrict__ Wo,
    uint2* __restrict__ dst, int nw4)
{
    int i = blockIdx.x * blockDim.x + threadIdx.x;
    if (i >= 4 * nw4) return;
    int w = i / nw4, j = i - w * nw4;
    const float4* src = (w == 0) ? Wq : (w == 1) ? Wk : (w == 2) ? Wv : Wo;
    float4 v = src[j];
    __half2 lo = __floats2half2_rn(v.x, v.y);
    __half2 hi = __floats2half2_rn(v.z, v.w);
    dst[i] = make_uint2(*(uint32_t*)&lo, *(uint32_t*)&hi);
}

// ============ reduce: out = p0 + p1 + bias =============================
__global__ void __launch_bounds__(256) reduce_bias(
    const float4* __restrict__ p0, const float4* __restrict__ p1,
    const float4* __restrict__ bias, float4* __restrict__ out, int n4)
{
    int i = blockIdx.x * blockDim.x + threadIdx.x;
    if (i < n4) {
        float4 a = p0[i], b = p1[i], bb = bias[i % (DIM / 4)];
        out[i] = make_float4(a.x + b.x + bb.x, a.y + b.y + bb.y,
                             a.z + b.z + bb.z, a.w + b.w + bb.w);
    }
}

// ================= fp16 GEMM core =================
#define GM_BM 128
#define GM_BN 128
#define GM_BK 64
#define GSTR_H 72
#define GM_TILE_H (GM_BM * GSTR_H)
#define GM_STAGE_H (2 * GM_TILE_H)
#define GM_SMEM_BYTES (3 * GM_STAGE_H * 2)   // 110592

__device__ __forceinline__ void gemm_tile_f16(
    const __half* __restrict__ A, const __half* __restrict__ B,
    const float* __restrict__ bias, float* __restrict__ Cf, __half* __restrict__ Ch,
    int M, int N, int K, int kbeg, int klen, int m0, int n0, __half* sm)
{
    const int tid = threadIdx.x;
    const int lane = tid & 31;
    const int wid = tid >> 5;
    const int wm = wid >> 2;
    const int wn = wid & 3;

    const int tr = lane & 7;
    const int mq = lane >> 3;
    const int a_row = tr + 8 * (mq & 1);
    const int a_kb  = 16 * (mq >> 1);
    const int b_row = tr + 8 * (mq >> 1);
    const int b_kb  = 16 * (mq & 1);

    int r2[4], kc2[4], arow[4], brow[4];
#pragma unroll
    for (int i = 0; i < 4; ++i) {
        int s = tid + i * 256;
        r2[i] = s >> 3;
        kc2[i] = (s & 7) * 8;
        arow[i] = min(m0 + r2[i], M - 1);
        brow[i] = n0 + r2[i];
    }

    const uint32_t smu = smem_addr(sm);

    auto fill = [&](int st, int k0) {
        const uint32_t base = smu + 2u * (st * GM_STAGE_H);
#pragma unroll
        for (int i = 0; i < 4; ++i)
            cp_async16(base + 2u * (r2[i] * GSTR_H + kc2[i]),
                       A + (size_t)arow[i] * K + k0 + kc2[i]);
#pragma unroll
        for (int i = 0; i < 4; ++i)
            cp_async16(base + 2u * (GM_TILE_H + r2[i] * GSTR_H + kc2[i]),
                       B + (size_t)brow[i] * K + k0 + kc2[i]);
        CP_COMMIT();
    };

    fill(0, kbeg);
    fill(1, kbeg + GM_BK);

    float acc[16][4];
#pragma unroll
    for (int t = 0; t < 16; ++t)
        acc[t][0] = acc[t][1] = acc[t][2] = acc[t][3] = 0.f;

    const int NIT = klen / GM_BK;
    int st = 0;
    for (int it = 0; it < NIT; ++it) {
        CP_WAIT1();
        __syncthreads();
        if (it + 2 < NIT) fill((st + 2) % 3, kbeg + (it + 2) * GM_BK);
        else CP_COMMIT();

        const uint32_t Ab = smu + 2u * (st * GM_STAGE_H);
        const uint32_t Bb = Ab + 2u * GM_TILE_H;
#pragma unroll
        for (int ks = 0; ks < 4; ++ks) {
            const int kbb = ks * 32;
            uint32_t af[4][4], bf[4][2];
#pragma unroll
            for (int mt = 0; mt < 4; ++mt) {
                uint32_t addr = Ab + (wm * 64 + mt * 16 + a_row) * (GSTR_H * 2) + kbb + a_kb;
                ldsm_x4(af[mt][0], af[mt][1], af[mt][2], af[mt][3], addr);
            }
#pragma unroll
            for (int p = 0; p < 2; ++p) {
                uint32_t addr = Bb + (wn * 32 + p * 16 + b_row) * (GSTR_H * 2) + kbb + b_kb;
                ldsm_x4(bf[2*p][0], bf[2*p][1], bf[2*p+1][0], bf[2*p+1][1], addr);
            }
#pragma unroll
            for (int mt = 0; mt < 4; ++mt)
#pragma unroll
                for (int nt = 0; nt < 4; ++nt)
                    mma_f16(acc[mt * 4 + nt],
                            af[mt][0], af[mt][1], af[mt][2], af[mt][3],
                            bf[nt][0], bf[nt][1]);
        }
        st = (st + 1) % 3;
    }

    // epilogue
#pragma unroll
    for (int nt = 0; nt < 4; ++nt) {
        int c = n0 + wn * 32 + nt * 8 + (lane & 3) * 2;
        float b0 = 0.f, b1 = 0.f;
        if (bias) { b0 = bias[c]; b1 = bias[c + 1]; }
#pragma unroll
        for (int mt = 0; mt < 4; ++mt) {
            int r = m0 + wm * 64 + mt * 16 + (lane >> 2);
            float* a4 = acc[mt * 4 + nt];
            if (Ch) {
                if (r < M)
                    *(__half2*)(Ch + (size_t)r * N + c) = __floats2half2_rn(a4[0] + b0, a4[1] + b1);
                if (r + 8 < M)
                    *(__half2*)(Ch + (size_t)(r + 8) * N + c) = __floats2half2_rn(a4[2] + b0, a4[3] + b1);
            } else {
                if (r < M)
                    *(float2*)(Cf + (size_t)r * N + c) = make_float2(a4[0] + b0, a4[1] + b1);
                if (r + 8 < M)
                    *(float2*)(Cf + (size_t)(r + 8) * N + c) = make_float2(a4[2] + b0, a4[3] + b1);
            }
        }
    }
}

__global__ void __launch_bounds__(256, 2) qkv_gemm_f16(
    const float* __restrict__ bq, const float* __restrict__ bk,
    const float* __restrict__ bv)
{
    extern __shared__ __align__(16) __half smh[];
    const float* b; __half* outH;
    if (blockIdx.z == 0)      { b = bq; outH = g_qh; }
    else if (blockIdx.z == 1) { b = bk; outH = g_kh; }
    else                      { b = bv; outH = g_vt; }
    gemm_tile_f16(g_xt, g_wt[blockIdx.z], b, nullptr, outH, LTOK, DIM, DIM,
                  0, DIM, blockIdx.y * GM_BM, blockIdx.x * GM_BN, smh);
}

__global__ void __launch_bounds__(256, 2) out_gemm_f16()
{
    extern __shared__ __align__(16) __half smh[];
    float* part = blockIdx.z ? g_p1 : g_p0;
    gemm_tile_f16(g_ot, g_wt[3], nullptr, part, nullptr, LTOK, DIM, DIM,
                  blockIdx.z * (DIM / 2), DIM / 2,
                  blockIdx.y * GM_BM, blockIdx.x * GM_BN, smh);
}

// ============ fused RMSNorm + RoPE (fp16 in/out, fast sincos) ===========
__global__ void __launch_bounds__(256) rmsnorm_rope(
    const float* __restrict__ gq, const float* __restrict__ gk,
    const float* __restrict__ freqs, const int* __restrict__ gsz)
{
    const int t = blockIdx.x;
    const int which = blockIdx.y;
    const __half* row = (which ? g_kh : g_qh) + (size_t)t * DIM;
    __half* rowo = (which ? g_kt : g_qt) + (size_t)t * DIM;
    const float oscale = which ? 1.0f : (SCALE * LOG2E);
    const float* g = which ? gk : gq;
    const int tid = threadIdx.x;

    float ss = 0.f;
    for (int i = tid; i < DIM / 2; i += 256) {
        float2 v = __half22float2(((const __half2*)row)[i]);
        ss += v.x * v.x + v.y * v.y;
    }
    __shared__ float red[8];
#pragma unroll
    for (int o = 16; o; o >>= 1) ss += __shfl_xor_sync(0xffffffffu, ss, o);
    if ((tid & 31) == 0) red[tid >> 5] = ss;
    __syncthreads();
    if (tid < 8) {
        float v = red[tid];
#pragma unroll
        for (int o = 4; o; o >>= 1) v += __shfl_xor_sync(0xffu, v, o);
        if (tid == 0) red[0] = v;
    }
    __syncthreads();
    const float rms = rsqrtf(red[0] * (1.0f / DIM) + EPS);

    const int Hs = gsz[1], Ws = gsz[2];
    const int fi = t / (Hs * Ws);
    const int hi = (t / Ws) % Hs;
    const int wi = t % Ws;

    for (int p = tid; p < HEADS * 64; p += 256) {
        const int h = p >> 6;
        const int j = p & 63;
        const int pos = (j < 22) ? fi : ((j < 43) ? hi : wi);
        const float ang = freqs[pos * 64 + j];
        float c, s;
        __sincosf(ang, &s, &c);   // HW MUFU approx; error ~1e-5, well under fp16 noise
        const int d0 = h * HD + 2 * j;
        float2 xv = __half22float2(*(const __half2*)(row + d0));
        const float x0 = xv.x * rms * g[d0];
        const float x1 = xv.y * rms * g[d0 + 1];
        __half2 o = __floats2half2_rn((x0 * c - x1 * s) * oscale,
                                      (x0 * s + x1 * c) * oscale);
        *(__half2*)(rowo + d0) = o;
    }
}

// ====== flash attention: BQ=64, 256 thr, 2 CTA/SM (R15 config) ==========
#define FQ 64
#define FK 64
#define TST_H 136
#define SST_H 72
#define FLASH_SMEM_BYTES (4*FQ*TST_H*2 + FQ*SST_H*2 + (2*FQ + 8*FQ)*4)

__global__ void __launch_bounds__(256, 2) flash_f16()
{
    extern __shared__ __align__(16) char smc[];
    __half* Qs = (__half*)smc;
    __half* K0 = Qs + FQ * TST_H;
    __half* K1 = K0 + FQ * TST_H;
    __half* Vs = K1 + FQ * TST_H;
    __half* Ss = Vs + FQ * TST_H;
    float* m_s = (float*)(Ss + FQ * SST_H);
    float* l_s = m_s + FQ;
    float* pm  = l_s + FQ;          // [64][4]
    float* ps  = pm + FQ * 4;       // [64][4]

    const int tid = threadIdx.x;
    const int lane = tid & 31;
    const int wid = tid >> 5;
    const int wm = wid >> 2;
    const int wn = wid & 3;
    const int h  = blockIdx.y;
    const int q0 = blockIdx.x * FQ;

    const int tr = lane & 7;
    const int mq = lane >> 3;
    const int a_row = tr + 8 * (mq & 1);
    const int a_kb  = 16 * (mq >> 1);
    const int b_row = tr + 8 * (mq >> 1);
    const int b_kb  = 16 * (mq & 1);
    const int v_krow = tr + 8 * (mq & 1);
    const int v_noff = 8 * (mq >> 1);

    const uint32_t Qa = smem_addr(Qs);
    const uint32_t K0a = smem_addr(K0);
    const uint32_t K1a = smem_addr(K1);
    const uint32_t Va = smem_addr(Vs);
    const uint32_t Sa = smem_addr(Ss);

    int srow[4], scol[4];
#pragma unroll
    for (int j = 0; j < 4; ++j) {
        int i = tid + j * 256;
        srow[j] = i >> 4;
        scol[j] = (i & 15) * 8;
    }

    // Q tile + K(0)
#pragma unroll
    for (int j = 0; j < 4; ++j) {
        uint4 v = *(const uint4*)(g_qt + (size_t)(q0 + srow[j]) * DIM + h * HD + scol[j]);
        *(uint4*)&Qs[srow[j] * TST_H + scol[j]] = v;
        uint4 kv = *(const uint4*)(g_kt + (size_t)srow[j] * DIM + h * HD + scol[j]);
        *(uint4*)&K0[srow[j] * TST_H + scol[j]] = kv;
    }
    if (tid < FQ) { m_s[tid] = -3.0e38f; l_s[tid] = 0.f; }

    float O[8][4];
#pragma unroll
    for (int t = 0; t < 8; ++t) O[t][0] = O[t][1] = O[t][2] = O[t][3] = 0.f;

    __syncthreads();

    int it = 0;
    for (int t0 = 0; t0 < LTOK; t0 += FK, ++it) {
        const uint32_t Kcur = (it & 1) ? K1a : K0a;
        __half* Knext = (it & 1) ? K0 : K1;

        uint4 vreg[4], kreg[4];
#pragma unroll
        for (int j = 0; j < 4; ++j)
            vreg[j] = *(const uint4*)(g_vt + (size_t)(t0 + srow[j]) * DIM + h * HD + scol[j]);
        const bool has_next = (t0 + FK < LTOK);
        if (has_next) {
#pragma unroll
            for (int j = 0; j < 4; ++j)
                kreg[j] = *(const uint4*)(g_kt + (size_t)(t0 + FK + srow[j]) * DIM + h * HD + scol[j]);
        }

        // S = Q K^T (log2-domain, fp32 accum)
        float Sacc[2][2][4] = {};
#pragma unroll
        for (int ks = 0; ks < 8; ++ks) {
            const int kbb = ks * 32;
            uint32_t af[2][4], bf[2][2];
#pragma unroll
            for (int mt = 0; mt < 2; ++mt) {
                uint32_t addr = Qa + (wm * 32 + mt * 16 + a_row) * (TST_H * 2) + kbb + a_kb;
                ldsm_x4(af[mt][0], af[mt][1], af[mt][2], af[mt][3], addr);
            }
            {
                uint32_t addr = Kcur + (wn * 16 + b_row) * (TST_H * 2) + kbb + b_kb;
                ldsm_x4(bf[0][0], bf[0][1], bf[1][0], bf[1][1], addr);
            }
#pragma unroll
            for (int mt = 0; mt < 2; ++mt)
#pragma unroll
                for (int nt = 0; nt < 2; ++nt)
                    mma_f16(Sacc[mt][nt],
                            af[mt][0], af[mt][1], af[mt][2], af[mt][3],
                            bf[nt][0], bf[nt][1]);
        }

        // warp-partial row max
        float pmax[2][2];
#pragma unroll
        for (int mt = 0; mt < 2; ++mt) {
            pmax[mt][0] = fmaxf(fmaxf(Sacc[mt][0][0], Sacc[mt][0][1]),
                                fmaxf(Sacc[mt][1][0], Sacc[mt][1][1]));
            pmax[mt][1] = fmaxf(fmaxf(Sacc[mt][0][2], Sacc[mt][0][3]),
                                fmaxf(Sacc[mt][1][2], Sacc[mt][1][3]));
#pragma unroll
            for (int rs = 0; rs < 2; ++rs) {
                pmax[mt][rs] = fmaxf(pmax[mt][rs], __shfl_xor_sync(0xffffffffu, pmax[mt][rs], 1));
                pmax[mt][rs] = fmaxf(pmax[mt][rs], __shfl_xor_sync(0xffffffffu, pmax[mt][rs], 2));
            }
        }
        if ((lane & 3) == 0) {
#pragma unroll
            for (int mt = 0; mt < 2; ++mt)
#pragma unroll
                for (int rs = 0; rs < 2; ++rs) {
                    int row = wm * 32 + mt * 16 + (lane >> 2) + rs * 8;
                    pm[row * 4 + wn] = pmax[mt][rs];
                }
        }
        __syncthreads();   // A

        // commit V(t), K(t+1)
#pragma unroll
        for (int j = 0; j < 4; ++j)
            *(uint4*)&Vs[srow[j] * TST_H + scol[j]] = vreg[j];
        if (has_next) {
#pragma unroll
            for (int j = 0; j < 4; ++j)
                *(uint4*)&Knext[srow[j] * TST_H + scol[j]] = kreg[j];
        }

        // softmax: mnew, f, P via ex2.f16x2
        float mnew[2][2], fsc[2][2], psum[2][2];
#pragma unroll
        for (int mt = 0; mt < 2; ++mt)
#pragma unroll
            for (int rs = 0; rs < 2; ++rs) {
                int row = wm * 32 + mt * 16 + (lane >> 2) + rs * 8;
                float4 pv = *(float4*)&pm[row * 4];
                float mold = m_s[row];
                float mx = fmaxf(fmaxf(pv.x, pv.y), fmaxf(pv.z, pv.w));
                float mn = fmaxf(mold, mx);
                mnew[mt][rs] = mn;
                fsc[mt][rs] = exp2f(mold - mn);
                psum[mt][rs] = 0.f;
            }
#pragma unroll
        for (int mt = 0; mt < 2; ++mt) {
            int r = wm * 32 + mt * 16 + (lane >> 2);
            int c = wn * 16 + (lane & 3) * 2;
#pragma unroll
            for (int nt = 0; nt < 2; ++nt) {
                __half2 s0 = __floats2half2_rn(Sacc[mt][nt][0] - mnew[mt][0],
                                               Sacc[mt][nt][1] - mnew[mt][0]);
                __half2 s1 = __floats2half2_rn(Sacc[mt][nt][2] - mnew[mt][1],
                                               Sacc[mt][nt][3] - mnew[mt][1]);
                uint32_t p0 = h2exp2(*(uint32_t*)&s0);
                uint32_t p1 = h2exp2(*(uint32_t*)&s1);
                *(uint32_t*)&Ss[r * SST_H + c + nt * 8] = p0;
                *(uint32_t*)&Ss[(r + 8) * SST_H + c + nt * 8] = p1;
                float2 f0 = __half22float2(*(__half2*)&p0);
                float2 f1 = __half22float2(*(__half2*)&p1);
                psum[mt][0] += f0.x + f0.y;
                psum[mt][1] += f1.x + f1.y;
            }
        }
#pragma unroll
        for (int mt = 0; mt < 2; ++mt)
#pragma unroll
            for (int rs = 0; rs < 2; ++rs) {
                psum[mt][rs] += __shfl_xor_sync(0xffffffffu, psum[mt][rs], 1);
                psum[mt][rs] += __shfl_xor_sync(0xffffffffu, psum[mt][rs], 2);
            }
        if ((lane & 3) == 0) {
#pragma unroll
            for (int mt = 0; mt < 2; ++mt)
#pragma unroll
                for (int rs = 0; rs < 2; ++rs) {
                    int row = wm * 32 + mt * 16 + (lane >> 2) + rs * 8;
                    ps[row * 4 + wn] = psum[mt][rs];
                }
        }

        // O rescale
#pragma unroll
        for (int mt = 0; mt < 2; ++mt) {
            float f0 = fsc[mt][0], f1 = fsc[mt][1];
#pragma unroll
            for (int nt = 0; nt < 4; ++nt) {
                O[mt * 4 + nt][0] *= f0; O[mt * 4 + nt][1] *= f0;
                O[mt * 4 + nt][2] *= f1; O[mt * 4 + nt][3] *= f1;
            }
        }
        __syncthreads();   // B

        if (wn == 0 && (lane & 3) == 0) {
#pragma unroll
            for (int mt = 0; mt < 2; ++mt)
#pragma unroll
                for (int rs = 0; rs < 2; ++rs) {
                    int row = wm * 32 + mt * 16 + (lane >> 2) + rs * 8;
                    float4 s4 = *(float4*)&ps[row * 4];
                    l_s[row] = l_s[row] * fsc[mt][rs] + (s4.x + s4.y + s4.z + s4.w);
                    m_s[row] = mnew[mt][rs];
                }
        }

        // O += P @ V
#pragma unroll
        for (int ks = 0; ks < 4; ++ks) {
            const int kb = ks * 16;
            uint32_t af[2][4], bf[4][2];
#pragma unroll
            for (int mt = 0; mt < 2; ++mt) {
                uint32_t addr = Sa + (wm * 32 + mt * 16 + a_row) * (SST_H * 2) + ks * 32 + a_kb;
                ldsm_x4(af[mt][0], af[mt][1], af[mt][2], af[mt][3], addr);
            }
#pragma unroll
            for (int p = 0; p < 2; ++p) {
                int c0 = wn * 32 + p * 16;
                uint32_t addr = Va + (kb + v_krow) * (TST_H * 2) + (c0 + v_noff) * 2;
                ldsm_x4_t(bf[2*p][0], bf[2*p][1], bf[2*p+1][0], bf[2*p+1][1], addr);
            }
#pragma unroll
            for (int mt = 0; mt < 2; ++mt)
#pragma unroll
                for (int nt = 0; nt < 4; ++nt)
                    mma_f16(O[mt * 4 + nt],
                            af[mt][0], af[mt][1], af[mt][2], af[mt][3],
                            bf[nt][0], bf[nt][1]);
        }
    }

    __syncthreads();

    // finalize -> fp16 g_ot
#pragma unroll
    for (int mt = 0; mt < 2; ++mt) {
        int r = wm * 32 + mt * 16 + (lane >> 2);
        float inv0 = 1.f / l_s[r], inv1 = 1.f / l_s[r + 8];
#pragma unroll
        for (int nt = 0; nt < 4; ++nt) {
            int c = wn * 32 + nt * 8 + (lane & 3) * 2;
            float* a4 = O[mt * 4 + nt];
            *(__half2*)(g_ot + (size_t)(q0 + r) * DIM + h * HD + c) =
                __floats2half2_rn(a4[0] * inv0, a4[1] * inv0);
            *(__half2*)(g_ot + (size_t)(q0 + r + 8) * DIM + h * HD + c) =
                __floats2half2_rn(a4[2] * inv1, a4[3] * inv1);
        }
    }
}

// ================= launch =================
extern "C" void kernel_launch(void* const* d_in, const int* in_sizes, int n_in,
                              void* d_out, int out_size)
{
    const float* x          = (const float*)d_in[0];
    const int*   grid_sizes = (const int*)d_in[2];
    const float* freqs      = (const float*)d_in[3];
    const float* Wq = (const float*)d_in[4];
    const float* bq = (const float*)d_in[5];
    const float* Wk = (const float*)d_in[6];
    const float* bk = (const float*)d_in[7];
    const float* Wv = (const float*)d_in[8];
    const float* bv = (const float*)d_in[9];
    const float* Wo = (const float*)d_in[10];
    const float* bo = (const float*)d_in[11];
    const float* gq = (const float*)d_in[12];
    const float* gk = (const float*)d_in[13];
    float* out = (float*)d_out;

    __half *xt, *wt;
    float *p0, *p1;
    cudaGetSymbolAddress((void**)&xt, g_xt);
    cudaGetSymbolAddress((void**)&wt, g_wt);
    cudaGetSymbolAddress((void**)&p0, g_p0);
    cudaGetSymbolAddress((void**)&p1, g_p1);

    cudaFuncSetAttribute(flash_f16, cudaFuncAttributeMaxDynamicSharedMemorySize, FLASH_SMEM_BYTES);
    cudaFuncSetAttribute(qkv_gemm_f16, cudaFuncAttributeMaxDynamicSharedMemorySize, GM_SMEM_BYTES);
    cudaFuncSetAttribute(out_gemm_f16, cudaFuncAttributeMaxDynamicSharedMemorySize, GM_SMEM_BYTES);

    const int NX4 = LTOK * DIM / 4;
    const int NW4 = DIM * DIM / 4;

    convert_f16<<<(NX4 + 255) / 256, 256>>>((const float4*)x, (uint2*)xt, NX4);
    convert_w4<<<(4 * NW4 + 255) / 256, 256>>>((const float4*)Wq, (const float4*)Wk,
                                               (const float4*)Wv, (const float4*)Wo,
                                               (uint2*)wt, NW4);

    dim3 gqkv(DIM / GM_BN, (LTOK + GM_BM - 1) / GM_BM, 3);
    dim3 gout(DIM / GM_BN, (LTOK + GM_BM - 1) / GM_BM, 2);

    qkv_gemm_f16<<<gqkv, 256, GM_SMEM_BYTES>>>(bq, bk, bv);
    rmsnorm_rope<<<dim3(LTOK, 2), 256>>>(gq, gk, freqs, grid_sizes);
    flash_f16<<<dim3(LTOK / FQ, HEADS), 256, FLASH_SMEM_BYTES>>>();
    out_gemm_f16<<<gout, 256, GM_SMEM_BYTES>>>();
    reduce_bias<<<(NX4 + 255) / 256, 256>>>((const float4*)p0, (const float4*)p1,
                                            (const float4*)bo, (float4*)out, NX4);
}